// round 6
// baseline (speedup 1.0000x reference)
#include <cuda_runtime.h>
#include <cuda_bf16.h>
#include <cstdint>
#include <cstddef>

// ---------------------------------------------------------------------------
// QLSTM  T=512 B=64 D=512 H=512
//  z_t = x_t@Wx + b4 + h_t@(Wh+R)
//  Phase A (prep):   split X and weights into bf16 hi/lo, permute columns
//  Phase B (gemm):   Z0[32768,2048] = X@Wx + b4   (3-product bf16 split)
//  Phase C (rnn):    persistent, 128 CTAs x 16 cols, 512 steps, flag sync.
//                    4-way K-split across warps (4 independent mma chains,
//                    SMEM reduction), Z0 prefetch hoisted above the poll.
//  Column permutation: z column for (hidden hc, gate g) stored at n = hc*4+g
// ---------------------------------------------------------------------------

#define TT 512
#define BB 64
#define DD 512
#define HH 512
#define NCOLS 2048
#define MTOT (TT * BB)          // 32768
#define RNN_CTAS 128
#define NPER 16                 // cols per rnn CTA

// ------------------------- static device scratch ---------------------------
__device__ __align__(128) __nv_bfloat16 g_Ax[(size_t)MTOT * 1024];   // X split  [m][hi|lo]
__device__ __align__(128) __nv_bfloat16 g_Bx[(size_t)NCOLS * 1024];  // Wx split [n][hi|lo]
__device__ __align__(128) __nv_bfloat16 g_Br[(size_t)NCOLS * 1024];  // (Wh+R)   [n][hi|lo]
__device__ __align__(128) float g_b4[NCOLS];
__device__ __align__(128) float g_Z0[(size_t)MTOT * NCOLS];          // 256 MB
__device__ __align__(128) __nv_bfloat16 g_hbuf[2 * BB * 1024];       // h split ping-pong
__device__ __align__(128) unsigned g_flags[RNN_CTAS * 32];           // 1 line / CTA

// ------------------------------ helpers ------------------------------------
__device__ __forceinline__ uint32_t smem_u32(const void* p) {
    return (uint32_t)__cvta_generic_to_shared(p);
}
__device__ __forceinline__ void ldsm_x4(uint32_t& r0, uint32_t& r1, uint32_t& r2,
                                        uint32_t& r3, uint32_t addr) {
    asm volatile("ldmatrix.sync.aligned.m8n8.x4.shared.b16 {%0,%1,%2,%3},[%4];\n"
                 : "=r"(r0), "=r"(r1), "=r"(r2), "=r"(r3) : "r"(addr));
}
__device__ __forceinline__ void ldsm_x2(uint32_t& r0, uint32_t& r1, uint32_t addr) {
    asm volatile("ldmatrix.sync.aligned.m8n8.x2.shared.b16 {%0,%1},[%2];\n"
                 : "=r"(r0), "=r"(r1) : "r"(addr));
}
__device__ __forceinline__ void mma16816(float* d, const uint32_t* a,
                                         uint32_t b0, uint32_t b1) {
    asm volatile(
        "mma.sync.aligned.m16n8k16.row.col.f32.bf16.bf16.f32 "
        "{%0,%1,%2,%3},{%4,%5,%6,%7},{%8,%9},{%0,%1,%2,%3};\n"
        : "+f"(d[0]), "+f"(d[1]), "+f"(d[2]), "+f"(d[3])
        : "r"(a[0]), "r"(a[1]), "r"(a[2]), "r"(a[3]), "r"(b0), "r"(b1));
}
__device__ __forceinline__ void cp16(void* s, const void* g) {
    asm volatile("cp.async.cg.shared.global [%0],[%1],16;\n"
                 :: "r"(smem_u32(s)), "l"(g));
}
__device__ __forceinline__ void cp_commit() {
    asm volatile("cp.async.commit_group;\n");
}
__device__ __forceinline__ float sigf(float x) { return 1.f / (1.f + __expf(-x)); }
__device__ __forceinline__ float tanhfast(float x) {
    return 2.f / (1.f + __expf(-2.f * x)) - 1.f;
}

// ------------------------------- prep X ------------------------------------
__global__ void k_prep_x(const float* __restrict__ x) {
    size_t stride = (size_t)gridDim.x * blockDim.x;
    for (size_t i = (size_t)blockIdx.x * blockDim.x + threadIdx.x;
         i < (size_t)MTOT * 512; i += stride) {
        size_t m = i >> 9, k = i & 511;
        float v = x[i];
        __nv_bfloat16 hi = __float2bfloat16(v);
        float r = v - __bfloat162float(hi);
        g_Ax[m * 1024 + k] = hi;
        g_Ax[m * 1024 + 512 + k] = __float2bfloat16(r);
    }
}

// ------------------------------- prep W ------------------------------------
__global__ void k_prep_w(const float* __restrict__ Wf, const float* __restrict__ bf,
                         const float* __restrict__ Wi, const float* __restrict__ bi,
                         const float* __restrict__ Wg, const float* __restrict__ bg,
                         const float* __restrict__ Wo, const float* __restrict__ bo,
                         const float* __restrict__ Rf, const float* __restrict__ Ri,
                         const float* __restrict__ Rg, const float* __restrict__ Ro) {
    int n = blockIdx.x;          // permuted column 0..2047
    int g = n & 3, hc = n >> 2;
    const float* W = (g == 0) ? Wf : (g == 1) ? Wi : (g == 2) ? Wg : Wo;
    const float* R = (g == 0) ? Rf : (g == 1) ? Ri : (g == 2) ? Rg : Ro;
    const float* bb = (g == 0) ? bf : (g == 1) ? bi : (g == 2) ? bg : bo;

    for (int k = threadIdx.x; k < 512; k += blockDim.x) {
        float wx = W[(size_t)k * 512 + hc];
        __nv_bfloat16 hi = __float2bfloat16(wx);
        g_Bx[(size_t)n * 1024 + k] = hi;
        g_Bx[(size_t)n * 1024 + 512 + k] =
            __float2bfloat16(wx - __bfloat162float(hi));

        float wh = W[(size_t)(512 + k) * 512 + hc] + R[(size_t)k * 512 + hc];
        __nv_bfloat16 hih = __float2bfloat16(wh);
        g_Br[(size_t)n * 1024 + k] = hih;
        g_Br[(size_t)n * 1024 + 512 + k] =
            __float2bfloat16(wh - __bfloat162float(hih));
    }
    if (threadIdx.x == 0) g_b4[n] = bb[hc];

    int gt = blockIdx.x * blockDim.x + threadIdx.x;
    if (gt < 2 * BB * 1024) g_hbuf[gt] = __float2bfloat16(0.f);  // h0 = 0
    if (gt < RNN_CTAS * 32) g_flags[gt] = 0;
}

// --------------------------- phase B: Z0 GEMM ------------------------------
// CTA tile 256x128, 16 warps (4m x 4n), warp tile 64x32. K chunks of 64, dbl buf.
#define P1_SA (256 * 72)
#define P1_SB (128 * 72)
#define P1_SMEM ((2 * P1_SA + 2 * P1_SB) * 2)

__global__ void __launch_bounds__(512, 1) k_gemm_x() {
    extern __shared__ __nv_bfloat16 smp[];
    __nv_bfloat16* sA = smp;                // [2][256*72]
    __nv_bfloat16* sB = smp + 2 * P1_SA;    // [2][128*72]
    const int m0 = blockIdx.x * 256, n0 = blockIdx.y * 128;
    const int tid = threadIdx.x, lane = tid & 31, w = tid >> 5;
    const int wm = w & 3, wn = w >> 2;      // 4 x 4
    const int tg = lane >> 2, t4 = lane & 3;

    float acc[4][4][4];
#pragma unroll
    for (int jt = 0; jt < 4; jt++) {
        int col = n0 + wn * 32 + jt * 8 + 2 * t4;
        float b0 = g_b4[col], b1 = g_b4[col + 1];
#pragma unroll
        for (int mt = 0; mt < 4; mt++) {
            acc[mt][jt][0] = b0; acc[mt][jt][1] = b1;
            acc[mt][jt][2] = b0; acc[mt][jt][3] = b1;
        }
    }

    auto issue = [&](int cc, int buf) {
        int seg = cc >> 3, kb = (cc & 7) * 64;
        int aoff = (seg == 1) ? 512 : 0, boff = (seg == 2) ? 512 : 0;
        size_t abase = (size_t)m0 * 1024 + aoff + kb;
#pragma unroll
        for (int u = tid; u < 2048; u += 512) {
            int r = u >> 3, c8 = (u & 7) * 8;
            cp16(&sA[buf * P1_SA + r * 72 + c8], &g_Ax[abase + (size_t)r * 1024 + c8]);
        }
        size_t bbase = (size_t)n0 * 1024 + boff + kb;
#pragma unroll
        for (int u = tid; u < 1024; u += 512) {
            int r = u >> 3, c8 = (u & 7) * 8;
            cp16(&sB[buf * P1_SB + r * 72 + c8], &g_Bx[bbase + (size_t)r * 1024 + c8]);
        }
        cp_commit();
    };

    issue(0, 0);
    for (int cc = 0; cc < 24; cc++) {
        int buf = cc & 1;
        if (cc < 23) {
            issue(cc + 1, buf ^ 1);
            asm volatile("cp.async.wait_group 1;\n");
        } else {
            asm volatile("cp.async.wait_group 0;\n");
        }
        __syncthreads();
#pragma unroll
        for (int kk = 0; kk < 4; kk++) {
            int ko = kk * 16;
            uint32_t a[4][4];
#pragma unroll
            for (int mt = 0; mt < 4; mt++) {
                int row = wm * 64 + mt * 16 + (lane & 15);
                int kx = ko + ((lane >> 4) << 3);
                ldsm_x4(a[mt][0], a[mt][1], a[mt][2], a[mt][3],
                        smem_u32(&sA[buf * P1_SA + row * 72 + kx]));
            }
#pragma unroll
            for (int jt = 0; jt < 4; jt++) {
                int nr = wn * 32 + jt * 8 + (lane & 7);
                int kx = ko + (((lane >> 3) & 1) << 3);
                uint32_t b0, b1;
                ldsm_x2(b0, b1, smem_u32(&sB[buf * P1_SB + nr * 72 + kx]));
#pragma unroll
                for (int mt = 0; mt < 4; mt++)
                    mma16816(acc[mt][jt], a[mt], b0, b1);
            }
        }
        __syncthreads();
    }

#pragma unroll
    for (int mt = 0; mt < 4; mt++) {
        int row = m0 + wm * 64 + mt * 16 + tg;
#pragma unroll
        for (int jt = 0; jt < 4; jt++) {
            int col = n0 + wn * 32 + jt * 8 + 2 * t4;
            *(float2*)&g_Z0[(size_t)row * 2048 + col] =
                make_float2(acc[mt][jt][0], acc[mt][jt][1]);
            *(float2*)&g_Z0[(size_t)(row + 8) * 2048 + col] =
                make_float2(acc[mt][jt][2], acc[mt][jt][3]);
        }
    }
}

// --------------------------- phase C: recurrence ---------------------------
// 128 CTAs x 256 thr. CTA j owns permuted cols [16j,16j+16) = hidden [4j,4j+4).
// 8 warps = (kw 0..3 K-quarter) x (wm 0..1 M-half). Warp tile M32 x N16 x K384.
// kw>0 warps write fp32 partials to SMEM; kw==0 warps reduce + gates.
#define ST2 1032
#define P2_WB (NPER * ST2)
#define P2_AB (64 * ST2)
// floats: sZ 2*1024, sP 2*3*4*32*4 = 3072, sH 64*4 = 256
#define P2_SMEM ((P2_WB + P2_AB) * 2 + (2048 + 3072 + 256) * 4)
#define HX_OFF ((size_t)TT * BB * HH)

__global__ void __launch_bounds__(256) k_rnn(float* __restrict__ out, int out_size) {
    extern __shared__ __nv_bfloat16 smp[];
    __nv_bfloat16* sB = smp;                     // [NPER][ST2]
    __nv_bfloat16* sA = smp + P2_WB;             // [64][ST2]
    float* sZ = (float*)(smp + P2_WB + P2_AB);   // [2][64*16]
    float* sP = sZ + 2048;                       // [2*3][4][32][4]
    float* sH = sP + 3072;                       // [64][4]
    const int j = blockIdx.x, n0c = j * NPER;
    const int tid = threadIdx.x, lane = tid & 31, w = tid >> 5;
    const int wm = w & 1;          // M half: rows [wm*32, wm*32+32)
    const int kw = w >> 1;         // K quarter 0..3
    const int tg = lane >> 2, t4 = lane & 3;
    const bool ev = (t4 & 1) == 0;

    // resident weight slice (NPER rows x 1024) for all 512 steps
    for (int u = tid; u < NPER * 128; u += 256) {
        int r = u >> 7, c8 = (u & 127) * 8;
        *(uint4*)&sB[r * ST2 + c8] = *(const uint4*)&g_Br[(size_t)(n0c + r) * 1024 + c8];
    }
    // prologue: Z(0) into sZ[0]
    {
        int r = tid >> 2, q = (tid & 3) * 4;
        cp16(&sZ[r * 16 + q], &g_Z0[(size_t)r * 2048 + n0c + q]);
    }
    cp_commit();
    asm volatile("cp.async.wait_group 0;\n");
    __syncthreads();

    const int asel = (lane >> 4) << 3;
    const int brow4 = ((lane >> 4) << 3) + (lane & 7);       // 0..15
    const int bsel4 = ((lane >> 3) & 1) << 3;

    float cst[2][2][2];            // [mt][jt][row01] cell state (kw==0 even lanes)
#pragma unroll
    for (int a1 = 0; a1 < 2; a1++)
#pragma unroll
        for (int a2 = 0; a2 < 2; a2++) { cst[a1][a2][0] = 0.f; cst[a1][a2][1] = 0.f; }

    float acc[2][2][4];            // [mt][jt][e]

    for (int t = 0; t < 512; t++) {
        int buf = t & 1, nb = buf ^ 1;

        // ---- group Z: prefetch Z0(t+1) (recurrence-independent, hoisted) ----
        {
            int tz = (t + 1) & 511;
            int r = tid >> 2, q = (tid & 3) * 4;
            cp16(&sZ[nb * 1024 + r * 16 + q],
                 &g_Z0[((size_t)tz * 64 + r) * 2048 + n0c + q]);
        }
        cp_commit();

        // ---- wait for all CTAs to have published h_t ----
        if (tid < RNN_CTAS) {
            const unsigned* fp = &g_flags[tid * 32];
            unsigned v;
            do {
                asm volatile("ld.acquire.gpu.global.u32 %0,[%1];" : "=r"(v) : "l"(fp));
            } while (v < (unsigned)t);
        }
        __syncthreads();   // S1: also protects sA/sH reuse across steps

        // ---- group c0: h hi half (64 x 512), group c1: h lo half ----
#pragma unroll
        for (int u = tid; u < 4096; u += 256) {
            int r = u >> 6, c8 = (u & 63) * 8;
            cp16(&sA[r * ST2 + c8], &g_hbuf[buf * 65536 + r * 1024 + c8]);
        }
        cp_commit();
#pragma unroll
        for (int u = tid; u < 4096; u += 256) {
            int r = u >> 6, c8 = (u & 63) * 8;
            cp16(&sA[r * ST2 + 512 + c8], &g_hbuf[buf * 65536 + r * 1024 + 512 + c8]);
        }
        cp_commit();

        // ---- accumulator init: kw0 warps take Z(t); others zero ----
        if (kw == 0) {
#pragma unroll
            for (int mt = 0; mt < 2; mt++) {
                int row = wm * 32 + mt * 16 + tg;
#pragma unroll
                for (int jt = 0; jt < 2; jt++) {
                    int lc = jt * 8 + 2 * t4;
                    float2 v0 = *(float2*)&sZ[buf * 1024 + row * 16 + lc];
                    float2 v1 = *(float2*)&sZ[buf * 1024 + (row + 8) * 16 + lc];
                    acc[mt][jt][0] = v0.x; acc[mt][jt][1] = v0.y;
                    acc[mt][jt][2] = v1.x; acc[mt][jt][3] = v1.y;
                }
            }
        } else {
#pragma unroll
            for (int mt = 0; mt < 2; mt++)
#pragma unroll
                for (int jt = 0; jt < 2; jt++)
#pragma unroll
                    for (int e = 0; e < 4; e++) acc[mt][jt][e] = 0.f;
        }

        // ---- GEMM: warp covers K quarter [kw*128, kw*128+128) of each seg ----
        auto seg = [&](int aoff, int boff) {
#pragma unroll
            for (int kk = 0; kk < 8; kk++) {
                int ko = kw * 128 + kk * 16;
                uint32_t a0[4], a1r[4], b[4];
                ldsm_x4(a0[0], a0[1], a0[2], a0[3],
                        smem_u32(&sA[(wm * 32 + (lane & 15)) * ST2 + aoff + ko + asel]));
                ldsm_x4(a1r[0], a1r[1], a1r[2], a1r[3],
                        smem_u32(&sA[(wm * 32 + 16 + (lane & 15)) * ST2 + aoff + ko + asel]));
                ldsm_x4(b[0], b[1], b[2], b[3],
                        smem_u32(&sB[brow4 * ST2 + boff + ko + bsel4]));
                mma16816(acc[0][0], a0, b[0], b[1]);
                mma16816(acc[0][1], a0, b[2], b[3]);
                mma16816(acc[1][0], a1r, b[0], b[1]);
                mma16816(acc[1][1], a1r, b[2], b[3]);
            }
        };

        asm volatile("cp.async.wait_group 1;\n");   // Z(t+1)+c0 done
        __syncthreads();                            // S2
        seg(0, 0);      // hi*hi
        seg(0, 512);    // hi*lo
        asm volatile("cp.async.wait_group 0;\n");   // c1 done
        __syncthreads();                            // S3
        seg(512, 0);    // lo*hi

        // ---- K reduction: kw>0 warps publish partials ----
        if (kw > 0) {
            int g34 = wm * 3 + (kw - 1);
#pragma unroll
            for (int mt = 0; mt < 2; mt++)
#pragma unroll
                for (int jt = 0; jt < 2; jt++) {
                    int f = mt * 2 + jt;
                    *(float4*)&sP[((g34 * 4 + f) * 32 + lane) * 4] =
                        make_float4(acc[mt][jt][0], acc[mt][jt][1],
                                    acc[mt][jt][2], acc[mt][jt][3]);
                }
        }
        __syncthreads();                            // S4

        if (kw == 0) {
            // reduce 3 partials
#pragma unroll
            for (int q = 0; q < 3; q++) {
                int g34 = wm * 3 + q;
#pragma unroll
                for (int mt = 0; mt < 2; mt++)
#pragma unroll
                    for (int jt = 0; jt < 2; jt++) {
                        int f = mt * 2 + jt;
                        float4 p = *(float4*)&sP[((g34 * 4 + f) * 32 + lane) * 4];
                        acc[mt][jt][0] += p.x; acc[mt][jt][1] += p.y;
                        acc[mt][jt][2] += p.z; acc[mt][jt][3] += p.w;
                    }
            }
            // gates: even t4 lane holds (f,i), odd holds (g,o), same (rows,hc)
#pragma unroll
            for (int mt = 0; mt < 2; mt++)
#pragma unroll
            for (int jt = 0; jt < 2; jt++) {
                float r0 = __shfl_xor_sync(0xffffffffu, acc[mt][jt][0], 1);
                float r1 = __shfl_xor_sync(0xffffffffu, acc[mt][jt][1], 1);
                float r2 = __shfl_xor_sync(0xffffffffu, acc[mt][jt][2], 1);
                float r3 = __shfl_xor_sync(0xffffffffu, acc[mt][jt][3], 1);
                float zf0 = ev ? acc[mt][jt][0] : r0, zi0 = ev ? acc[mt][jt][1] : r1;
                float zg0 = ev ? r0 : acc[mt][jt][0], zo0 = ev ? r1 : acc[mt][jt][1];
                float zf1 = ev ? acc[mt][jt][2] : r2, zi1 = ev ? acc[mt][jt][3] : r3;
                float zg1 = ev ? r2 : acc[mt][jt][2], zo1 = ev ? r3 : acc[mt][jt][3];

                float c0 = sigf(zf0) * cst[mt][jt][0] + sigf(zi0) * tanhfast(zg0);
                float c1 = sigf(zf1) * cst[mt][jt][1] + sigf(zi1) * tanhfast(zg1);
                cst[mt][jt][0] = c0; cst[mt][jt][1] = c1;
                float h0 = sigf(zo0) * tanhfast(c0);
                float h1 = sigf(zo1) * tanhfast(c1);

                if (ev) {
                    int b0r = wm * 32 + mt * 16 + tg, b1r = b0r + 8;
                    int hcl = jt * 2 + (t4 >> 1);
                    sH[b0r * 4 + hcl] = h0;
                    sH[b1r * 4 + hcl] = h1;
                    if (t == 511) {
                        int hcg = 4 * j + hcl;
                        if (HX_OFF + 32768 <= (size_t)out_size) {
                            out[HX_OFF + (size_t)b0r * 512 + hcg] = h0;
                            out[HX_OFF + (size_t)b1r * 512 + hcg] = h1;
                        }
                        if (HX_OFF + 65536 <= (size_t)out_size) {
                            out[HX_OFF + 32768 + (size_t)b0r * 512 + hcg] = c0;
                            out[HX_OFF + 32768 + (size_t)b1r * 512 + hcg] = c1;
                        }
                    }
                }
            }
        }
        __syncthreads();                            // S5

        // ---- h writes: out (fp32) + hi/lo split into next h buffer ----
        {
            int b = tid >> 2, hcl = tid & 3;
            float hv = sH[b * 4 + hcl];
            out[((size_t)t * 64 + b) * 512 + 4 * j + hcl] = hv;
            __nv_bfloat16 hi = __float2bfloat16(hv);
            __nv_bfloat16 lo = __float2bfloat16(hv - __bfloat162float(hi));
            g_hbuf[nb * 65536 + b * 1024 + 4 * j + hcl] = hi;
            g_hbuf[nb * 65536 + b * 1024 + 512 + 4 * j + hcl] = lo;
        }
        __syncthreads();                            // S6

        // publish h_{t+1}: release store to our flag
        if (tid == 0) {
            asm volatile("st.release.gpu.global.u32 [%0],%1;"
                         :: "l"(&g_flags[j * 32]), "r"((unsigned)(t + 1)));
        }
    }
}

// ------------------------------- launch ------------------------------------
extern "C" void kernel_launch(void* const* d_in, const int* in_sizes, int n_in,
                              void* d_out, int out_size) {
    const float* x  = (const float*)d_in[0];
    const float* Wf = (const float*)d_in[1];
    const float* bf = (const float*)d_in[2];
    const float* Wi = (const float*)d_in[3];
    const float* bi = (const float*)d_in[4];
    const float* Wg = (const float*)d_in[5];
    const float* bg = (const float*)d_in[6];
    const float* Wo = (const float*)d_in[7];
    const float* bo = (const float*)d_in[8];
    const float* Rf = (const float*)d_in[9];
    const float* Ri = (const float*)d_in[10];
    const float* Rg = (const float*)d_in[11];
    const float* Ro = (const float*)d_in[12];

    cudaFuncSetAttribute(k_gemm_x, cudaFuncAttributeMaxDynamicSharedMemorySize, P1_SMEM);
    cudaFuncSetAttribute(k_rnn, cudaFuncAttributeMaxDynamicSharedMemorySize, P2_SMEM);

    k_prep_x<<<4096, 256>>>(x);
    k_prep_w<<<2048, 256>>>(Wf, bf, Wi, bi, Wg, bg, Wo, bo, Rf, Ri, Rg, Ro);
    k_gemm_x<<<dim3(128, 16), 512, P1_SMEM>>>();
    k_rnn<<<RNN_CTAS, 256, P2_SMEM>>>((float*)d_out, out_size);
}